// round 14
// baseline (speedup 1.0000x reference)
#include <cuda_runtime.h>
#include <cuda_fp16.h>
#include <cstdint>

#define BB 2
#define NQ 900
#define CC 256
#define HH 8
#define NN 4096
#define DH 32
#define KSPLIT 2

// -------- scratch --------
__device__ float  g_q  [BB*NQ*CC];          // scaled Q projection (scale*log2e)
__device__ uint2  g_wqf[16384], g_wkf[16384], g_wvf[16384];
__device__ uint2  g_wpfh[16384], g_wpfl[16384];
__device__ uint2  g_w2fh[2048], g_w2fl[2048];
__device__ uint2  g_kf[BB*HH*512*2*32];     // [bh][kt8][lane][ds]
__device__ uint2  g_vf[BB*HH*256*4*32];     // [bh][kt16][lane][nt]
__device__ unsigned g_mb[BB*128];
__device__ float  g_rx[BB*HH*NQ*64];        // scaled by log2e
__device__ float  g_ry[BB*HH*NQ*64];        // scaled by log2e
__device__ float  g_aop[KSPLIT*BB*NQ*CC];   // raw partial O
__device__ float  g_lp [KSPLIT*BB*HH*NQ];   // partial l
__device__ __half g_aoh[BB*NQ*CC];
__device__ __half g_aol[BB*NQ*CC];

__device__ __forceinline__ uint32_t pack_h2(float lo, float hi){
    uint32_t r; asm("cvt.rn.f16x2.f32 %0, %1, %2;" : "=r"(r) : "f"(hi), "f"(lo)); return r;
}
__device__ __forceinline__ float lo_f(uint32_t x){ return __low2float(*(__half2*)&x); }
__device__ __forceinline__ float hi_f(uint32_t x){ return __high2float(*(__half2*)&x); }
__device__ __forceinline__ float ex2f(float x){ float r; asm("ex2.approx.f32 %0, %1;":"=f"(r):"f"(x)); return r; }
__device__ __forceinline__ void mma16816(float* c, const uint32_t* a, uint2 b){
    asm volatile("mma.sync.aligned.m16n8k16.row.col.f32.f16.f16.f32 "
      "{%0,%1,%2,%3}, {%4,%5,%6,%7}, {%8,%9}, {%0,%1,%2,%3};"
      : "+f"(c[0]),"+f"(c[1]),"+f"(c[2]),"+f"(c[3])
      : "r"(a[0]),"r"(a[1]),"r"(a[2]),"r"(a[3]),"r"(b.x),"r"(b.y));
}
__device__ __forceinline__ uint32_t smem_u32(const void* p){
    uint32_t a; asm("{ .reg .u64 t; cvta.to.shared.u64 t, %1; cvt.u32.u64 %0, t; }":"=r"(a):"l"(p)); return a;
}
__device__ __forceinline__ void cpa16(uint32_t dst, const void* src){
    asm volatile("cp.async.cg.shared.global [%0], [%1], 16;"::"r"(dst),"l"(src));
}
__device__ __forceinline__ void cpa_commit(){ asm volatile("cp.async.commit_group;":::"memory"); }
template<int N> __device__ __forceinline__ void cpa_wait(){ asm volatile("cp.async.wait_group %0;"::"n"(N):"memory"); }

#define L2E 1.4426950408889634f

// =================================================================
// Launch 0: prep (packW x4 [0,256), packW2 [256,264), mask [264])
// =================================================================
__global__ __launch_bounds__(256) void prep_kernel(
    const float* __restrict__ Wq, const float* __restrict__ Wk, const float* __restrict__ Wv,
    const float* __restrict__ Wp, const float* __restrict__ W2x, const float* __restrict__ W2y,
    const unsigned char* __restrict__ mask,
    uint2* __restrict__ wqf, uint2* __restrict__ wkf, uint2* __restrict__ wvf,
    uint2* __restrict__ wpfh, uint2* __restrict__ wpfl,
    uint2* __restrict__ w2fh, uint2* __restrict__ w2fl, unsigned* __restrict__ mb)
{
    const int blk=blockIdx.x, tid=threadIdx.x;
    if (blk < 256){
        const float* W; uint2 *fh, *fl=nullptr;
        int base;
        if (blk < 64){ W=Wq; fh=wqf; base=0; }
        else if (blk < 128){ W=Wk; fh=wkf; base=64; }
        else if (blk < 192){ W=Wv; fh=wvf; base=128; }
        else { W=Wp; fh=wpfh; fl=wpfl; base=192; }
        int idx=(blk-base)*256+tid;
        int lane=idx&31, ks=(idx>>5)&15, n8=idx>>9;
        int k0=ks*16+(lane&3)*2, n=n8*8+(lane>>2);
        float w00=W[k0*256+n], w01=W[(k0+1)*256+n], w08=W[(k0+8)*256+n], w09=W[(k0+9)*256+n];
        uint2 hi=make_uint2(pack_h2(w00,w01), pack_h2(w08,w09));
        fh[idx]=hi;
        if (fl) fl[idx]=make_uint2(pack_h2(w00-lo_f(hi.x), w01-hi_f(hi.x)),
                                   pack_h2(w08-lo_f(hi.y), w09-hi_f(hi.y)));
        return;
    }
    if (blk < 264){
        int idx=(blk-256)*256+tid;
        int axis=idx>>10, r=idx&1023, lane=r&31, ks=r>>5;
        int j0=ks*16+(lane&3)*2, h=lane>>2;
        const float* W2=axis?W2y:W2x;
        float w00=W2[j0*8+h], w01=W2[(j0+1)*8+h], w08=W2[(j0+8)*8+h], w09=W2[(j0+9)*8+h];
        uint2 hi=make_uint2(pack_h2(w00,w01), pack_h2(w08,w09));
        w2fh[idx]=hi;
        w2fl[idx]=make_uint2(pack_h2(w00-lo_f(hi.x), w01-hi_f(hi.x)),
                             pack_h2(w08-lo_f(hi.y), w09-hi_f(hi.y)));
        return;
    }
    if (tid < BB*128){
        const unsigned char* p=mask+tid*32;
        unsigned v=0;
        #pragma unroll
        for (int i=0;i<32;i++) v |= (p[i]?1u:0u)<<i;
        mb[tid]=v;
    }
}

// =================================================================
// Launch 1: FUSED projections + RPE.  grid 3336.
// =================================================================
__global__ __launch_bounds__(256) void mid_kernel(
    const float* __restrict__ qa, const float* __restrict__ ka, const float* __restrict__ va,
    const uint2* __restrict__ wq, const uint2* __restrict__ wk, const uint2* __restrict__ wv,
    const float* __restrict__ bq, const float* __restrict__ bk, const float* __restrict__ bv,
    float* __restrict__ qout, uint2* __restrict__ Kf, uint2* __restrict__ Vf, float qscale,
    const float* __restrict__ ref,
    const float* __restrict__ W1x, const float* __restrict__ b1x,
    const float* __restrict__ W1y, const float* __restrict__ b1y,
    const uint2* __restrict__ w2fh, const uint2* __restrict__ w2fl,
    float* __restrict__ rx, float* __restrict__ ry)
{
    __shared__ char sraw[9216];
    const int blk=blockIdx.x, tid=threadIdx.x;
    const int wid=tid>>5, lane=tid&31, g=lane>>2, tg=lane&3;

    if (blk < 1536){
        __half (*vs)[72] = (__half(*)[72])sraw;
        const int z=blk>>9, rem=blk&511;
        const int bn=(rem&3)*64, bm=(rem>>2)*64;
        const float* A; const uint2* Wf; const float* bias; int M;
        if (z==0){ A=qa; Wf=wq; bias=bq; M=BB*NQ; }
        else if (z==1){ A=ka; Wf=wk; bias=bk; M=BB*NN; }
        else { A=va; Wf=wv; bias=bv; M=BB*NN; }
        if (bm >= M) return;
        const int wrow=wid>>1, wcol=wid&1;
        const int r0=bm+wrow*16+g, r1=r0+8;
        const int r0c=r0<M?r0:M-1, r1c=r1<M?r1:M-1;
        const uint2* wf=Wf+((bn>>3)+wcol*4)*512+lane;
        float c[4][4]={};
        #pragma unroll
        for (int ks=0;ks<16;ks++){
            const int k0=ks*16+tg*2;
            float2 v0=*(const float2*)&A[r0c*256+k0];
            float2 v1=*(const float2*)&A[r1c*256+k0];
            float2 v2=*(const float2*)&A[r0c*256+k0+8];
            float2 v3=*(const float2*)&A[r1c*256+k0+8];
            uint32_t a[4];
            a[0]=pack_h2(v0.x,v0.y);
            a[1]=pack_h2(v1.x,v1.y);
            a[2]=pack_h2(v2.x,v2.y);
            a[3]=pack_h2(v3.x,v3.y);
            #pragma unroll
            for (int nt=0;nt<4;nt++) mma16816(c[nt], a, wf[nt*512+ks*32]);
        }
        const int cn=bn+wcol*32;
        if (z==0){
            #pragma unroll
            for (int nt=0;nt<4;nt++){
                int col=cn+nt*8+tg*2;
                float b0=bias[col], b1=bias[col+1];
                if (r0<M){ float2 o=make_float2((c[nt][0]+b0)*qscale,(c[nt][1]+b1)*qscale); *(float2*)&qout[r0*256+col]=o; }
                if (r1<M){ float2 o=make_float2((c[nt][2]+b0)*qscale,(c[nt][3]+b1)*qscale); *(float2*)&qout[r1*256+col]=o; }
            }
        } else if (z==1){
            // Kf layout: [bh][kt8][lane][ds]
            const int b=r0>>12;
            const int kt8a=(r0&4095)>>3;
            const int h=(bn>>5)+wcol;
            const size_t base=(size_t)(b*8+h)*32768;
            #pragma unroll
            for (int ds=0;ds<2;ds++){
                const int nlo=2*ds, nhi=2*ds+1;
                int clo=cn+nlo*8+tg*2, chi=cn+nhi*8+tg*2;
                float blo0=bias[clo], blo1=bias[clo+1];
                float bhi0=bias[chi], bhi1=bias[chi+1];
                Kf[base + (size_t)kt8a*64 + lane*2 + ds] = make_uint2(
                    pack_h2(c[nlo][0]+blo0, c[nlo][1]+blo1),
                    pack_h2(c[nhi][0]+bhi0, c[nhi][1]+bhi1));
                Kf[base + (size_t)(kt8a+1)*64 + lane*2 + ds] = make_uint2(
                    pack_h2(c[nlo][2]+blo0, c[nlo][3]+blo1),
                    pack_h2(c[nhi][2]+bhi0, c[nhi][3]+bhi1));
            }
        } else {
            // Vf layout: [bh][kt16][lane][nt]
            const int rl0=r0&63, rl1=rl0+8;
            #pragma unroll
            for (int nt=0;nt<4;nt++){
                int col=cn+nt*8+tg*2;
                float b0=bias[col], b1=bias[col+1];
                int cl=col&63;
                *(__half2*)&vs[rl0][cl]=__floats2half2_rn(c[nt][0]+b0,c[nt][1]+b1);
                *(__half2*)&vs[rl1][cl]=__floats2half2_rn(c[nt][2]+b0,c[nt][3]+b1);
            }
            __syncthreads();
            const int b=bm>>12;
            const int hloc=tid>>7;
            const int kt16loc=(tid>>5)&3;
            const int lane2=tid&31;
            const int h=(bn>>5)+hloc;
            const int kt16=((bm&4095)>>4)+kt16loc;
            const int key0=kt16loc*16+(lane2&3)*2;
            const size_t vb=(size_t)(b*8+h)*32768 + (size_t)kt16*128;
            #pragma unroll
            for (int nt=0;nt<4;nt++){
                int d=hloc*32+nt*8+(lane2>>2);
                uint2 o;
                o.x=(uint32_t)__half_as_ushort(vs[key0][d])   | ((uint32_t)__half_as_ushort(vs[key0+1][d])<<16);
                o.y=(uint32_t)__half_as_ushort(vs[key0+8][d]) | ((uint32_t)__half_as_ushort(vs[key0+9][d])<<16);
                Vf[vb + lane2*4 + nt]=o;
            }
        }
        return;
    }

    // ---------------- RPE ----------------
    float2 (*sAB)[512] = (float2(*)[512])sraw;
    const int bq2=blk-1536, b=bq2/NQ, q=bq2-b*NQ;
    float4 box=*(const float4*)&ref[bq2*4];
    float lox=box.x-box.z*0.5f, hix=box.x+box.z*0.5f;
    float loy=box.y-box.w*0.5f, hiy=box.y+box.w*0.5f;
    for (int idx=tid; idx<1024; idx+=256){
        int axis=idx>>9, j=idx&511;
        const float* W1=axis?W1y:W1x;
        float u=W1[j], v=W1[512+j];
        float bb=(axis?b1y:b1x)[j];
        float LO=axis?loy:lox, HI=axis?hiy:hix;
        sAB[axis][j]=make_float2(fmaf(LO,u,fmaf(HI,v,bb)), u+v);
    }
    __syncthreads();
    const int axis=wid>>2, mt=wid&3;
    const float p0=((float)(mt*16+g)+0.5f)*16.f;
    const float p1=p0+128.f;
    const uint2* fh=w2fh+axis*1024+lane;
    const uint2* fl=w2fl+axis*1024+lane;
    const float2* AB=sAB[axis];
    float c[4]={0.f,0.f,0.f,0.f};
    #pragma unroll 4
    for (int ks=0;ks<32;ks++){
        int j0=ks*16+tg*2;
        float2 ab0=AB[j0], ab1=AB[j0+1], ab8=AB[j0+8], ab9=AB[j0+9];
        float h00=fmaxf(fmaf(-p0,ab0.y,ab0.x),0.f);
        float h01=fmaxf(fmaf(-p0,ab1.y,ab1.x),0.f);
        float h10=fmaxf(fmaf(-p1,ab0.y,ab0.x),0.f);
        float h11=fmaxf(fmaf(-p1,ab1.y,ab1.x),0.f);
        float h08=fmaxf(fmaf(-p0,ab8.y,ab8.x),0.f);
        float h09=fmaxf(fmaf(-p0,ab9.y,ab9.x),0.f);
        float h18=fmaxf(fmaf(-p1,ab8.y,ab8.x),0.f);
        float h19=fmaxf(fmaf(-p1,ab9.y,ab9.x),0.f);
        uint32_t ah[4], al[4];
        ah[0]=pack_h2(h00,h01); ah[1]=pack_h2(h10,h11);
        ah[2]=pack_h2(h08,h09); ah[3]=pack_h2(h18,h19);
        al[0]=pack_h2(h00-lo_f(ah[0]), h01-hi_f(ah[0]));
        al[1]=pack_h2(h10-lo_f(ah[1]), h11-hi_f(ah[1]));
        al[2]=pack_h2(h08-lo_f(ah[2]), h09-hi_f(ah[2]));
        al[3]=pack_h2(h18-lo_f(ah[3]), h19-hi_f(ah[3]));
        uint2 bh=fh[ks*32], bl=fl[ks*32];
        mma16816(c, ah, bh);
        mma16816(c, ah, bl);
        mma16816(c, al, bh);
    }
    float* outp=axis?ry:rx;
    const int h2=tg*2, pos0=mt*16+g;
    size_t base0=((size_t)(b*8+h2)*NQ+q)*64;
    size_t base1=((size_t)(b*8+h2+1)*NQ+q)*64;
    outp[base0+pos0]    =c[0]*L2E;
    outp[base1+pos0]    =c[1]*L2E;
    outp[base0+pos0+8]  =c[2]*L2E;
    outp[base1+pos0+8]  =c[3]*L2E;
}

// =================================================================
// Launch 2: HMMA flash attention. 3-buffer cp.async pipeline,
// one sync/tile, uint4 fragment loads.  grid (8,16,2)
// =================================================================
__global__ __launch_bounds__(256) void attn_hmma_kernel(
    const float* __restrict__ qp, const uint2* __restrict__ Kf, const uint2* __restrict__ Vf,
    const float* __restrict__ rxg, const float* __restrict__ ryg,
    const unsigned* __restrict__ mbits, float* __restrict__ aop, float* __restrict__ lp)
{
    __shared__ uint2 sbuf[3][2048];   // [buf][ kf 1024 | vf 1024 ] = 3 x 16KB
    const int tid=threadIdx.x, wid=tid>>5, lane=tid&31;
    const int g=lane>>2, tg=lane&3;
    const int bh=blockIdx.y, b=bh>>3, h=bh&7;
    const int z=blockIdx.z;
    const int q0=blockIdx.x*128 + wid*16;
    int qr[2]={q0+g, q0+g+8};
    int qc[2]={qr[0]<NQ?qr[0]:NQ-1, qr[1]<NQ?qr[1]:NQ-1};

    const uint2* KfB=Kf+(size_t)bh*32768;
    const uint2* VfB=Vf+(size_t)bh*32768;
    const uint32_t sb0=smem_u32(sbuf);

    // prologue: prefetch tiles z*16 and z*16+1 into buf0/buf1
    #pragma unroll
    for (int pp=0;pp<2;pp++){
        const char* ks_=(const char*)(KfB+(size_t)(z*16+pp)*1024);
        const char* vs_=(const char*)(VfB+(size_t)(z*16+pp)*1024);
        uint32_t d=sb0+pp*16384+tid*16;
        cpa16(d,        ks_+tid*16);
        cpa16(d+4096,   ks_+4096+tid*16);
        cpa16(d+8192,   vs_+tid*16);
        cpa16(d+12288,  vs_+4096+tid*16);
        cpa_commit();
    }

    uint32_t qf[2][4];
    #pragma unroll
    for (int ds=0;ds<2;ds++)
        #pragma unroll
        for (int r=0;r<2;r++){
            const float* p=qp+((size_t)b*NQ+qc[r])*CC+h*32+ds*16+tg*2;
            qf[ds][r]  =pack_h2(p[0],p[1]);
            qf[ds][r+2]=pack_h2(p[8],p[9]);
        }

    float rxv[2][16], shift[2];
    #pragma unroll
    for (int r=0;r<2;r++){
        const float* rp=rxg+((size_t)bh*NQ+qc[r])*64;
        float mx=-1e30f;
        #pragma unroll
        for (int j=0;j<8;j++){
            float2 v=*(const float2*)&rp[j*8+tg*2];
            rxv[r][j*2]=v.x; rxv[r][j*2+1]=v.y;
            mx=fmaxf(mx,fmaxf(v.x,v.y));
        }
        mx=fmaxf(mx,__shfl_xor_sync(0xffffffffu,mx,1));
        mx=fmaxf(mx,__shfl_xor_sync(0xffffffffu,mx,2));
        const float* yp=ryg+((size_t)bh*NQ+qc[r])*64;
        float my=-1e30f;
        #pragma unroll
        for (int j=0;j<16;j++) my=fmaxf(my,yp[tg+4*j]);
        my=fmaxf(my,__shfl_xor_sync(0xffffffffu,my,1));
        my=fmaxf(my,__shfl_xor_sync(0xffffffffu,my,2));
        shift[r]=mx+my;
    }

    const uint2 onesb = (lane<4)? make_uint2(0x3C003C00u,0x3C003C00u) : make_uint2(0u,0u);
    float Oacc[4][4];
    #pragma unroll
    for (int i=0;i<4;i++)
        #pragma unroll
        for (int j=0;j<4;j++) Oacc[i][j]=0.f;
    float ls[4]={0.f,0.f,0.f,0.f};

    for (int tt=0; tt<16; tt++){
        const int t=z*16+tt;
        if (tt<15) cpa_wait<1>(); else cpa_wait<0>();
        __syncthreads();
        if (tt+2<16){
            const char* ks_=(const char*)(KfB+(size_t)(t+2)*1024);
            const char* vs_=(const char*)(VfB+(size_t)(t+2)*1024);
            uint32_t d=sb0+(uint32_t)((tt+2)%3)*16384+tid*16;
            cpa16(d,        ks_+tid*16);
            cpa16(d+4096,   ks_+4096+tid*16);
            cpa16(d+8192,   vs_+tid*16);
            cpa16(d+12288,  vs_+4096+tid*16);
            cpa_commit();
        }

        const uint2* kbuf=sbuf[tt%3];
        const uint2* vbuf=kbuf+1024;

        float cp0[2][2];
        #pragma unroll
        for (int r=0;r<2;r++){
            const float* yp=ryg+((size_t)bh*NQ+qc[r])*64+2*t;
            cp0[r][0]=yp[0]-shift[r];
            cp0[r][1]=yp[1]-shift[r];
        }
        unsigned mbw[4];
        #pragma unroll
        for (int j=0;j<4;j++) mbw[j]=mbits[b*128+t*4+j];

        if ((mbw[0]|mbw[1]|mbw[2]|mbw[3])==0u){
            // -------- fast path --------
            #pragma unroll
            for (int ks=0;ks<8;ks++){
                const int yp=ks>>2;
                float sc[2][4];
                #pragma unroll
                for (int j=0;j<2;j++){
                    const int nt=2*ks+j;
                    #pragma unroll
                    for (int i=0;i<4;i++){
                        const int row=i>>1, e=i&1;
                        sc[j][i]=rxv[row][(nt&7)*2+e]+cp0[row][yp];
                    }
                }
                #pragma unroll
                for (int j=0;j<2;j++){
                    uint4 kk=*(const uint4*)(kbuf+(size_t)(2*ks+j)*64+lane*2);
                    mma16816(sc[j], qf[0], make_uint2(kk.x,kk.y));
                    mma16816(sc[j], qf[1], make_uint2(kk.z,kk.w));
                }
                uint32_t pa[4];
                pa[0]=pack_h2(ex2f(sc[0][0]),ex2f(sc[0][1]));
                pa[1]=pack_h2(ex2f(sc[0][2]),ex2f(sc[0][3]));
                pa[2]=pack_h2(ex2f(sc[1][0]),ex2f(sc[1][1]));
                pa[3]=pack_h2(ex2f(sc[1][2]),ex2f(sc[1][3]));
                mma16816(ls, pa, onesb);
                const uint2* vp=vbuf+ks*128+lane*4;
                uint4 va=*(const uint4*)vp, vb2=*(const uint4*)(vp+2);
                mma16816(Oacc[0], pa, make_uint2(va.x,va.y));
                mma16816(Oacc[1], pa, make_uint2(va.z,va.w));
                mma16816(Oacc[2], pa, make_uint2(vb2.x,vb2.y));
                mma16816(Oacc[3], pa, make_uint2(vb2.z,vb2.w));
            }
        } else {
            // -------- general path --------
            float cp1[2][2];
            #pragma unroll
            for (int r=0;r<2;r++){
                cp1[r][0]=cp0[r][0]-144.26950408889634f;
                cp1[r][1]=cp0[r][1]-144.26950408889634f;
            }
            #pragma unroll
            for (int ks=0;ks<8;ks++){
                float sc[2][4];
                #pragma unroll
                for (int j=0;j<2;j++)
                    #pragma unroll
                    for (int i=0;i<4;i++) sc[j][i]=0.f;
                #pragma unroll
                for (int j=0;j<2;j++){
                    uint4 kk=*(const uint4*)(kbuf+(size_t)(2*ks+j)*64+lane*2);
                    mma16816(sc[j], qf[0], make_uint2(kk.x,kk.y));
                    mma16816(sc[j], qf[1], make_uint2(kk.z,kk.w));
                }
                float pv[2][4];
                const int yp=ks>>2;
                #pragma unroll
                for (int j=0;j<2;j++){
                    const int nt=2*ks+j;
                    #pragma unroll
                    for (int i=0;i<4;i++){
                        const int row=i>>1, e=i&1;
                        bool mbit=(mbw[nt>>2]>>((nt&3)*8+tg*2+e))&1u;
                        float s=sc[j][i]+rxv[row][(nt&7)*2+e];
                        float cp=mbit?cp1[row][yp]:cp0[row][yp];
                        pv[j][i]=ex2f(s+cp);
                    }
                }
                uint32_t pa[4];
                pa[0]=pack_h2(pv[0][0],pv[0][1]);
                pa[1]=pack_h2(pv[0][2],pv[0][3]);
                pa[2]=pack_h2(pv[1][0],pv[1][1]);
                pa[3]=pack_h2(pv[1][2],pv[1][3]);
                mma16816(ls, pa, onesb);
                const uint2* vp=vbuf+ks*128+lane*4;
                uint4 va=*(const uint4*)vp, vb2=*(const uint4*)(vp+2);
                mma16816(Oacc[0], pa, make_uint2(va.x,va.y));
                mma16816(Oacc[1], pa, make_uint2(va.z,va.w));
                mma16816(Oacc[2], pa, make_uint2(vb2.x,vb2.y));
                mma16816(Oacc[3], pa, make_uint2(vb2.z,vb2.w));
            }
        }
    }

    if (tg==0){
        if (qr[0]<NQ) lp[(size_t)z*BB*HH*NQ + (size_t)bh*NQ + qr[0]] = ls[0];
        if (qr[1]<NQ) lp[(size_t)z*BB*HH*NQ + (size_t)bh*NQ + qr[1]] = ls[2];
    }
    #pragma unroll
    for (int r=0;r<2;r++){
        if (qr[r]<NQ){
            float* dst=aop + (size_t)z*BB*NQ*CC + ((size_t)b*NQ+qr[r])*CC + h*32;
            #pragma unroll
            for (int nv=0;nv<4;nv++){
                float2 o=make_float2(Oacc[nv][2*r], Oacc[nv][2*r+1]);
                *(float2*)&dst[nv*8+tg*2]=o;
            }
        }
    }
}

// =================================================================
// Launch 3: combine partials + normalize (shfl-shared rcp) + hi/lo split
// =================================================================
__global__ __launch_bounds__(256) void pack_ao_kernel(
    const float* __restrict__ aop, const float* __restrict__ lp,
    __half* __restrict__ oh, __half* __restrict__ ol)
{
    int i=blockIdx.x*256+threadIdx.x;
    if (i < BB*NQ*CC){
        const int lane=threadIdx.x&31;
        float inv=0.f;
        if (lane==0){
            int bq=i>>8, q=bq%NQ, b=bq/NQ, h=(i>>5)&7;
            size_t li=(size_t)(b*8+h)*NQ+q;
            float l=lp[li]+lp[(size_t)BB*HH*NQ+li];
            inv=1.f/l;
        }
        inv=__shfl_sync(0xffffffffu,inv,0);
        float v=(aop[i]+aop[(size_t)BB*NQ*CC+i])*inv;
        __half hh=__float2half_rn(v);
        oh[i]=hh; ol[i]=__float2half_rn(v-__half2float(hh));
    }
}

// =================================================================
// Launch 4: output projection, 3-term hi/lo HMMA. grid (4,57) x128thr
// =================================================================
__global__ __launch_bounds__(128) void gemm_h3_kernel(
    const __half* __restrict__ Ah, const __half* __restrict__ Al,
    const uint2* __restrict__ Wfh, const uint2* __restrict__ Wfl,
    const float* __restrict__ bias, float* __restrict__ out, int M)
{
    const int tid=threadIdx.x, wid=tid>>5, lane=tid&31;
    const int g=lane>>2, tg=lane&3;
    const int wrow=wid>>1, wcol=wid&1;
    const int bm=blockIdx.y*32, bn=blockIdx.x*64;
    const int r0=bm+wrow*16+g, r1=r0+8;
    const int r0c=r0<M?r0:M-1, r1c=r1<M?r1:M-1;
    const int fbase=((bn>>3)+wcol*4)*512+lane;
    float c[4][4]={};
    #pragma unroll
    for (int ks=0;ks<16;ks++){
        const int k0=ks*16+tg*2;
        uint32_t ah[4], al[4];
        ah[0]=*(const uint32_t*)&Ah[r0c*256+k0];
        ah[1]=*(const uint32_t*)&Ah[r1c*256+k0];
        ah[2]=*(const uint32_t*)&Ah[r0c*256+k0+8];
        ah[3]=*(const uint32_t*)&Ah[r1c*256+k0+8];
        al[0]=*(const uint32_t*)&Al[r0c*256+k0];
        al[1]=*(const uint32_t*)&Al[r1c*256+k0];
        al[2]=*(const uint32_t*)&Al[r0c*256+k0+8];
        al[3]=*(const uint32_t*)&Al[r1c*256+k0+8];
        #pragma unroll
        for (int nt=0;nt<4;nt++){
            uint2 bh=Wfh[fbase+nt*512+ks*32];
            uint2 bl=Wfl[fbase+nt*512+ks*32];
            mma16816(c[nt], ah, bh);
            mma16816(c[nt], ah, bl);
            mma16816(c[nt], al, bh);
        }
    }
    const int cn=bn+wcol*32;
    #pragma unroll
    for (int nt=0;nt<4;nt++){
        int col=cn+nt*8+tg*2;
        float b0=bias[col], b1=bias[col+1];
        if (r0<M){ float2 o=make_float2(c[nt][0]+b0,c[nt][1]+b1); *(float2*)&out[r0*256+col]=o; }
        if (r1<M){ float2 o=make_float2(c[nt][2]+b0,c[nt][3]+b1); *(float2*)&out[r1*256+col]=o; }
    }
}

// ---------------- launch ----------------
extern "C" void kernel_launch(void* const* d_in, const int* in_sizes, int n_in,
                              void* d_out, int out_size)
{
    const float* query=(const float*)d_in[1];
    const float* ref  =(const float*)d_in[2];
    const float* kin  =(const float*)d_in[3];
    const float* vin  =(const float*)d_in[4];
    const unsigned char* mask=(const unsigned char*)d_in[6];
    const float* W1x=(const float*)d_in[7];
    const float* b1x=(const float*)d_in[8];
    const float* W2x=(const float*)d_in[9];
    const float* W1y=(const float*)d_in[10];
    const float* b1y=(const float*)d_in[11];
    const float* W2y=(const float*)d_in[12];
    const float* Wq =(const float*)d_in[13];
    const float* bq =(const float*)d_in[14];
    const float* Wk =(const float*)d_in[15];
    const float* bk =(const float*)d_in[16];
    const float* Wv =(const float*)d_in[17];
    const float* bv =(const float*)d_in[18];
    const float* Wp =(const float*)d_in[19];
    const float* bp =(const float*)d_in[20];
    float* out=(float*)d_out;

    void *pq,*pwq,*pwk,*pwv,*pwph,*pwpl,*pw2h,*pw2l;
    void *pkf,*pvf,*pmb,*prx,*pry,*paop,*plp,*paoh,*paol;
    cudaGetSymbolAddress(&pq,  g_q);
    cudaGetSymbolAddress(&pwq, g_wqf);
    cudaGetSymbolAddress(&pwk, g_wkf);
    cudaGetSymbolAddress(&pwv, g_wvf);
    cudaGetSymbolAddress(&pwph,g_wpfh);
    cudaGetSymbolAddress(&pwpl,g_wpfl);
    cudaGetSymbolAddress(&pw2h,g_w2fh);
    cudaGetSymbolAddress(&pw2l,g_w2fl);
    cudaGetSymbolAddress(&pkf, g_kf);
    cudaGetSymbolAddress(&pvf, g_vf);
    cudaGetSymbolAddress(&pmb, g_mb);
    cudaGetSymbolAddress(&prx, g_rx);
    cudaGetSymbolAddress(&pry, g_ry);
    cudaGetSymbolAddress(&paop,g_aop);
    cudaGetSymbolAddress(&plp, g_lp);
    cudaGetSymbolAddress(&paoh,g_aoh);
    cudaGetSymbolAddress(&paol,g_aol);

    const float qscale=(float)(0.17677669529663687 * 1.4426950408889634);
    const int MQ=BB*NQ;

    prep_kernel<<<265,256>>>(Wq,Wk,Wv,Wp,W2x,W2y,mask,
        (uint2*)pwq,(uint2*)pwk,(uint2*)pwv,(uint2*)pwph,(uint2*)pwpl,
        (uint2*)pw2h,(uint2*)pw2l,(unsigned*)pmb);
    mid_kernel<<<3336,256>>>(query,kin,vin,
        (const uint2*)pwq,(const uint2*)pwk,(const uint2*)pwv,bq,bk,bv,
        (float*)pq,(uint2*)pkf,(uint2*)pvf,qscale,
        ref,W1x,b1x,W1y,b1y,
        (const uint2*)pw2h,(const uint2*)pw2l,(float*)prx,(float*)pry);
    attn_hmma_kernel<<<dim3(8,BB*HH,KSPLIT),256>>>(
        (const float*)pq,(const uint2*)pkf,(const uint2*)pvf,
        (const float*)prx,(const float*)pry,(const unsigned*)pmb,(float*)paop,(float*)plp);
    pack_ao_kernel<<<(MQ*CC+255)/256,256>>>((const float*)paop,(const float*)plp,(__half*)paoh,(__half*)paol);
    gemm_h3_kernel<<<dim3(4,(MQ+31)/32),128>>>((const __half*)paoh,(const __half*)paol,
        (const uint2*)pwph,(const uint2*)pwpl,bp,out,MQ);
}

// round 15
// speedup vs baseline: 1.0003x; 1.0003x over previous
#include <cuda_runtime.h>
#include <cuda_fp16.h>
#include <cstdint>

#define BB 2
#define NQ 900
#define CC 256
#define HH 8
#define NN 4096
#define DH 32
#define KSPLIT 2

// -------- scratch --------
__device__ float  g_q  [BB*NQ*CC];
__device__ uint2  g_wqf[16384], g_wkf[16384], g_wvf[16384];
__device__ uint2  g_wpfh[16384], g_wpfl[16384];
__device__ uint2  g_w2fh[2048], g_w2fl[2048];
__device__ uint2  g_kf[BB*HH*512*2*32];     // [bh][kt8][lane][ds]
__device__ uint2  g_vf[BB*HH*256*4*32];     // [bh][kt16][lane][nt]
__device__ unsigned g_mb[BB*128];
__device__ float  g_rx[BB*HH*NQ*64];
__device__ float  g_ry[BB*HH*NQ*64];
__device__ float  g_aop[KSPLIT*BB*NQ*CC];
__device__ float  g_lp [KSPLIT*BB*HH*NQ];
__device__ __half g_aoh[BB*NQ*CC];
__device__ __half g_aol[BB*NQ*CC];

__device__ __forceinline__ uint32_t pack_h2(float lo, float hi){
    uint32_t r; asm("cvt.rn.f16x2.f32 %0, %1, %2;" : "=r"(r) : "f"(hi), "f"(lo)); return r;
}
__device__ __forceinline__ float lo_f(uint32_t x){ return __low2float(*(__half2*)&x); }
__device__ __forceinline__ float hi_f(uint32_t x){ return __high2float(*(__half2*)&x); }
__device__ __forceinline__ float ex2f(float x){ float r; asm("ex2.approx.f32 %0, %1;":"=f"(r):"f"(x)); return r; }
__device__ __forceinline__ void mma16816(float* c, const uint32_t* a, uint2 b){
    asm volatile("mma.sync.aligned.m16n8k16.row.col.f32.f16.f16.f32 "
      "{%0,%1,%2,%3}, {%4,%5,%6,%7}, {%8,%9}, {%0,%1,%2,%3};"
      : "+f"(c[0]),"+f"(c[1]),"+f"(c[2]),"+f"(c[3])
      : "r"(a[0]),"r"(a[1]),"r"(a[2]),"r"(a[3]),"r"(b.x),"r"(b.y));
}
__device__ __forceinline__ uint32_t smem_u32(const void* p){
    uint32_t a; asm("{ .reg .u64 t; cvta.to.shared.u64 t, %1; cvt.u32.u64 %0, t; }":"=r"(a):"l"(p)); return a;
}
__device__ __forceinline__ void cpa16(uint32_t dst, const void* src){
    asm volatile("cp.async.cg.shared.global [%0], [%1], 16;"::"r"(dst),"l"(src));
}
__device__ __forceinline__ void cpa_commit(){ asm volatile("cp.async.commit_group;":::"memory"); }
template<int N> __device__ __forceinline__ void cpa_wait(){ asm volatile("cp.async.wait_group %0;"::"n"(N):"memory"); }

#define L2E 1.4426950408889634f

// =================================================================
// Launch 0: prep
// =================================================================
__global__ __launch_bounds__(256) void prep_kernel(
    const float* __restrict__ Wq, const float* __restrict__ Wk, const float* __restrict__ Wv,
    const float* __restrict__ Wp, const float* __restrict__ W2x, const float* __restrict__ W2y,
    const unsigned char* __restrict__ mask,
    uint2* __restrict__ wqf, uint2* __restrict__ wkf, uint2* __restrict__ wvf,
    uint2* __restrict__ wpfh, uint2* __restrict__ wpfl,
    uint2* __restrict__ w2fh, uint2* __restrict__ w2fl, unsigned* __restrict__ mb)
{
    const int blk=blockIdx.x, tid=threadIdx.x;
    if (blk < 256){
        const float* W; uint2 *fh, *fl=nullptr;
        int base;
        if (blk < 64){ W=Wq; fh=wqf; base=0; }
        else if (blk < 128){ W=Wk; fh=wkf; base=64; }
        else if (blk < 192){ W=Wv; fh=wvf; base=128; }
        else { W=Wp; fh=wpfh; fl=wpfl; base=192; }
        int idx=(blk-base)*256+tid;
        int lane=idx&31, ks=(idx>>5)&15, n8=idx>>9;
        int k0=ks*16+(lane&3)*2, n=n8*8+(lane>>2);
        float w00=W[k0*256+n], w01=W[(k0+1)*256+n], w08=W[(k0+8)*256+n], w09=W[(k0+9)*256+n];
        uint2 hi=make_uint2(pack_h2(w00,w01), pack_h2(w08,w09));
        fh[idx]=hi;
        if (fl) fl[idx]=make_uint2(pack_h2(w00-lo_f(hi.x), w01-hi_f(hi.x)),
                                   pack_h2(w08-lo_f(hi.y), w09-hi_f(hi.y)));
        return;
    }
    if (blk < 264){
        int idx=(blk-256)*256+tid;
        int axis=idx>>10, r=idx&1023, lane=r&31, ks=r>>5;
        int j0=ks*16+(lane&3)*2, h=lane>>2;
        const float* W2=axis?W2y:W2x;
        float w00=W2[j0*8+h], w01=W2[(j0+1)*8+h], w08=W2[(j0+8)*8+h], w09=W2[(j0+9)*8+h];
        uint2 hi=make_uint2(pack_h2(w00,w01), pack_h2(w08,w09));
        w2fh[idx]=hi;
        w2fl[idx]=make_uint2(pack_h2(w00-lo_f(hi.x), w01-hi_f(hi.x)),
                             pack_h2(w08-lo_f(hi.y), w09-hi_f(hi.y)));
        return;
    }
    if (tid < BB*128){
        const unsigned char* p=mask+tid*32;
        unsigned v=0;
        #pragma unroll
        for (int i=0;i<32;i++) v |= (p[i]?1u:0u)<<i;
        mb[tid]=v;
    }
}

// =================================================================
// Launch 1: FUSED projections + RPE.  grid 3336.
// =================================================================
__global__ __launch_bounds__(256) void mid_kernel(
    const float* __restrict__ qa, const float* __restrict__ ka, const float* __restrict__ va,
    const uint2* __restrict__ wq, const uint2* __restrict__ wk, const uint2* __restrict__ wv,
    const float* __restrict__ bq, const float* __restrict__ bk, const float* __restrict__ bv,
    float* __restrict__ qout, uint2* __restrict__ Kf, uint2* __restrict__ Vf, float qscale,
    const float* __restrict__ ref,
    const float* __restrict__ W1x, const float* __restrict__ b1x,
    const float* __restrict__ W1y, const float* __restrict__ b1y,
    const uint2* __restrict__ w2fh, const uint2* __restrict__ w2fl,
    float* __restrict__ rx, float* __restrict__ ry)
{
    __shared__ char sraw[9216];
    const int blk=blockIdx.x, tid=threadIdx.x;
    const int wid=tid>>5, lane=tid&31, g=lane>>2, tg=lane&3;

    if (blk < 1536){
        __half (*vs)[72] = (__half(*)[72])sraw;
        const int z=blk>>9, rem=blk&511;
        const int bn=(rem&3)*64, bm=(rem>>2)*64;
        const float* A; const uint2* Wf; const float* bias; int M;
        if (z==0){ A=qa; Wf=wq; bias=bq; M=BB*NQ; }
        else if (z==1){ A=ka; Wf=wk; bias=bk; M=BB*NN; }
        else { A=va; Wf=wv; bias=bv; M=BB*NN; }
        if (bm >= M) return;
        const int wrow=wid>>1, wcol=wid&1;
        const int r0=bm+wrow*16+g, r1=r0+8;
        const int r0c=r0<M?r0:M-1, r1c=r1<M?r1:M-1;
        const uint2* wf=Wf+((bn>>3)+wcol*4)*512+lane;
        float c[4][4]={};
        #pragma unroll
        for (int ks=0;ks<16;ks++){
            const int k0=ks*16+tg*2;
            float2 v0=*(const float2*)&A[r0c*256+k0];
            float2 v1=*(const float2*)&A[r1c*256+k0];
            float2 v2=*(const float2*)&A[r0c*256+k0+8];
            float2 v3=*(const float2*)&A[r1c*256+k0+8];
            uint32_t a[4];
            a[0]=pack_h2(v0.x,v0.y);
            a[1]=pack_h2(v1.x,v1.y);
            a[2]=pack_h2(v2.x,v2.y);
            a[3]=pack_h2(v3.x,v3.y);
            #pragma unroll
            for (int nt=0;nt<4;nt++) mma16816(c[nt], a, wf[nt*512+ks*32]);
        }
        const int cn=bn+wcol*32;
        if (z==0){
            #pragma unroll
            for (int nt=0;nt<4;nt++){
                int col=cn+nt*8+tg*2;
                float b0=bias[col], b1=bias[col+1];
                if (r0<M){ float2 o=make_float2((c[nt][0]+b0)*qscale,(c[nt][1]+b1)*qscale); *(float2*)&qout[r0*256+col]=o; }
                if (r1<M){ float2 o=make_float2((c[nt][2]+b0)*qscale,(c[nt][3]+b1)*qscale); *(float2*)&qout[r1*256+col]=o; }
            }
        } else if (z==1){
            const int b=r0>>12;
            const int kt8a=(r0&4095)>>3;
            const int h=(bn>>5)+wcol;
            const size_t base=(size_t)(b*8+h)*32768;
            #pragma unroll
            for (int ds=0;ds<2;ds++){
                const int nlo=2*ds, nhi=2*ds+1;
                int clo=cn+nlo*8+tg*2, chi=cn+nhi*8+tg*2;
                float blo0=bias[clo], blo1=bias[clo+1];
                float bhi0=bias[chi], bhi1=bias[chi+1];
                Kf[base + (size_t)kt8a*64 + lane*2 + ds] = make_uint2(
                    pack_h2(c[nlo][0]+blo0, c[nlo][1]+blo1),
                    pack_h2(c[nhi][0]+bhi0, c[nhi][1]+bhi1));
                Kf[base + (size_t)(kt8a+1)*64 + lane*2 + ds] = make_uint2(
                    pack_h2(c[nlo][2]+blo0, c[nlo][3]+blo1),
                    pack_h2(c[nhi][2]+bhi0, c[nhi][3]+bhi1));
            }
        } else {
            const int rl0=r0&63, rl1=rl0+8;
            #pragma unroll
            for (int nt=0;nt<4;nt++){
                int col=cn+nt*8+tg*2;
                float b0=bias[col], b1=bias[col+1];
                int cl=col&63;
                *(__half2*)&vs[rl0][cl]=__floats2half2_rn(c[nt][0]+b0,c[nt][1]+b1);
                *(__half2*)&vs[rl1][cl]=__floats2half2_rn(c[nt][2]+b0,c[nt][3]+b1);
            }
            __syncthreads();
            const int b=bm>>12;
            const int hloc=tid>>7;
            const int kt16loc=(tid>>5)&3;
            const int lane2=tid&31;
            const int h=(bn>>5)+hloc;
            const int kt16=((bm&4095)>>4)+kt16loc;
            const int key0=kt16loc*16+(lane2&3)*2;
            const size_t vb=(size_t)(b*8+h)*32768 + (size_t)kt16*128;
            #pragma unroll
            for (int nt=0;nt<4;nt++){
                int d=hloc*32+nt*8+(lane2>>2);
                uint2 o;
                o.x=(uint32_t)__half_as_ushort(vs[key0][d])   | ((uint32_t)__half_as_ushort(vs[key0+1][d])<<16);
                o.y=(uint32_t)__half_as_ushort(vs[key0+8][d]) | ((uint32_t)__half_as_ushort(vs[key0+9][d])<<16);
                Vf[vb + lane2*4 + nt]=o;
            }
        }
        return;
    }

    // ---------------- RPE ----------------
    float2 (*sAB)[512] = (float2(*)[512])sraw;
    const int bq2=blk-1536, b=bq2/NQ, q=bq2-b*NQ;
    float4 box=*(const float4*)&ref[bq2*4];
    float lox=box.x-box.z*0.5f, hix=box.x+box.z*0.5f;
    float loy=box.y-box.w*0.5f, hiy=box.y+box.w*0.5f;
    for (int idx=tid; idx<1024; idx+=256){
        int axis=idx>>9, j=idx&511;
        const float* W1=axis?W1y:W1x;
        float u=W1[j], v=W1[512+j];
        float bb=(axis?b1y:b1x)[j];
        float LO=axis?loy:lox, HI=axis?hiy:hix;
        sAB[axis][j]=make_float2(fmaf(LO,u,fmaf(HI,v,bb)), u+v);
    }
    __syncthreads();
    const int axis=wid>>2, mt=wid&3;
    const float p0=((float)(mt*16+g)+0.5f)*16.f;
    const float p1=p0+128.f;
    const uint2* fh=w2fh+axis*1024+lane;
    const uint2* fl=w2fl+axis*1024+lane;
    const float2* AB=sAB[axis];
    float c[4]={0.f,0.f,0.f,0.f};
    #pragma unroll 4
    for (int ks=0;ks<32;ks++){
        int j0=ks*16+tg*2;
        float2 ab0=AB[j0], ab1=AB[j0+1], ab8=AB[j0+8], ab9=AB[j0+9];
        float h00=fmaxf(fmaf(-p0,ab0.y,ab0.x),0.f);
        float h01=fmaxf(fmaf(-p0,ab1.y,ab1.x),0.f);
        float h10=fmaxf(fmaf(-p1,ab0.y,ab0.x),0.f);
        float h11=fmaxf(fmaf(-p1,ab1.y,ab1.x),0.f);
        float h08=fmaxf(fmaf(-p0,ab8.y,ab8.x),0.f);
        float h09=fmaxf(fmaf(-p0,ab9.y,ab9.x),0.f);
        float h18=fmaxf(fmaf(-p1,ab8.y,ab8.x),0.f);
        float h19=fmaxf(fmaf(-p1,ab9.y,ab9.x),0.f);
        uint32_t ah[4], al[4];
        ah[0]=pack_h2(h00,h01); ah[1]=pack_h2(h10,h11);
        ah[2]=pack_h2(h08,h09); ah[3]=pack_h2(h18,h19);
        al[0]=pack_h2(h00-lo_f(ah[0]), h01-hi_f(ah[0]));
        al[1]=pack_h2(h10-lo_f(ah[1]), h11-hi_f(ah[1]));
        al[2]=pack_h2(h08-lo_f(ah[2]), h09-hi_f(ah[2]));
        al[3]=pack_h2(h18-lo_f(ah[3]), h19-hi_f(ah[3]));
        uint2 bh=fh[ks*32], bl=fl[ks*32];
        mma16816(c, ah, bh);
        mma16816(c, ah, bl);
        mma16816(c, al, bh);
    }
    float* outp=axis?ry:rx;
    const int h2=tg*2, pos0=mt*16+g;
    size_t base0=((size_t)(b*8+h2)*NQ+q)*64;
    size_t base1=((size_t)(b*8+h2+1)*NQ+q)*64;
    outp[base0+pos0]    =c[0]*L2E;
    outp[base1+pos0]    =c[1]*L2E;
    outp[base0+pos0+8]  =c[2]*L2E;
    outp[base1+pos0+8]  =c[3]*L2E;
}

// =================================================================
// Launch 2: HMMA flash attention. 128 threads / 64 queries per CTA,
// grid (15, 16, 2) = 480 CTAs -> 4 CTAs/SM, all 148 SMs in one wave.
// 3-buffer cp.async pipeline, one sync/tile, uint4 fragment loads.
// =================================================================
__global__ __launch_bounds__(128) void attn_hmma_kernel(
    const float* __restrict__ qp, const uint2* __restrict__ Kf, const uint2* __restrict__ Vf,
    const float* __restrict__ rxg, const float* __restrict__ ryg,
    const unsigned* __restrict__ mbits, float* __restrict__ aop, float* __restrict__ lp)
{
    __shared__ uint2 sbuf[3][2048];   // 3 x 16KB
    const int tid=threadIdx.x, wid=tid>>5, lane=tid&31;
    const int g=lane>>2, tg=lane&3;
    const int bh=blockIdx.y, b=bh>>3, h=bh&7;
    const int z=blockIdx.z;
    const int q0=blockIdx.x*64 + wid*16;
    int qr[2]={q0+g, q0+g+8};
    int qc[2]={qr[0]<NQ?qr[0]:NQ-1, qr[1]<NQ?qr[1]:NQ-1};

    const uint2* KfB=Kf+(size_t)bh*32768;
    const uint2* VfB=Vf+(size_t)bh*32768;
    const uint32_t sb0=smem_u32(sbuf);

    // prologue: prefetch tiles z*16, z*16+1 into buf0/buf1 (128 threads: 8 x 16B each per tile)
    #pragma unroll
    for (int pp=0;pp<2;pp++){
        const char* ks_=(const char*)(KfB+(size_t)(z*16+pp)*1024);
        const char* vs_=(const char*)(VfB+(size_t)(z*16+pp)*1024);
        uint32_t d=sb0+pp*16384+tid*16;
        #pragma unroll
        for (int j2=0;j2<4;j2++){
            cpa16(d+j2*2048,      ks_+tid*16+j2*2048);
            cpa16(d+8192+j2*2048, vs_+tid*16+j2*2048);
        }
        cpa_commit();
    }

    uint32_t qf[2][4];
    #pragma unroll
    for (int ds=0;ds<2;ds++)
        #pragma unroll
        for (int r=0;r<2;r++){
            const float* p=qp+((size_t)b*NQ+qc[r])*CC+h*32+ds*16+tg*2;
            qf[ds][r]  =pack_h2(p[0],p[1]);
            qf[ds][r+2]=pack_h2(p[8],p[9]);
        }

    float rxv[2][16], shift[2];
    #pragma unroll
    for (int r=0;r<2;r++){
        const float* rp=rxg+((size_t)bh*NQ+qc[r])*64;
        float mx=-1e30f;
        #pragma unroll
        for (int j=0;j<8;j++){
            float2 v=*(const float2*)&rp[j*8+tg*2];
            rxv[r][j*2]=v.x; rxv[r][j*2+1]=v.y;
            mx=fmaxf(mx,fmaxf(v.x,v.y));
        }
        mx=fmaxf(mx,__shfl_xor_sync(0xffffffffu,mx,1));
        mx=fmaxf(mx,__shfl_xor_sync(0xffffffffu,mx,2));
        const float* yp=ryg+((size_t)bh*NQ+qc[r])*64;
        float my=-1e30f;
        #pragma unroll
        for (int j=0;j<16;j++) my=fmaxf(my,yp[tg+4*j]);
        my=fmaxf(my,__shfl_xor_sync(0xffffffffu,my,1));
        my=fmaxf(my,__shfl_xor_sync(0xffffffffu,my,2));
        shift[r]=mx+my;
    }

    const uint2 onesb = (lane<4)? make_uint2(0x3C003C00u,0x3C003C00u) : make_uint2(0u,0u);
    float Oacc[4][4];
    #pragma unroll
    for (int i=0;i<4;i++)
        #pragma unroll
        for (int j=0;j<4;j++) Oacc[i][j]=0.f;
    float ls[4]={0.f,0.f,0.f,0.f};

    for (int tt=0; tt<16; tt++){
        const int t=z*16+tt;
        if (tt<15) cpa_wait<1>(); else cpa_wait<0>();
        __syncthreads();
        if (tt+2<16){
            const char* ks_=(const char*)(KfB+(size_t)(t+2)*1024);
            const char* vs_=(const char*)(VfB+(size_t)(t+2)*1024);
            uint32_t d=sb0+(uint32_t)((tt+2)%3)*16384+tid*16;
            #pragma unroll
            for (int j2=0;j2<4;j2++){
                cpa16(d+j2*2048,      ks_+tid*16+j2*2048);
                cpa16(d+8192+j2*2048, vs_+tid*16+j2*2048);
            }
            cpa_commit();
        }

        const uint2* kbuf=sbuf[tt%3];
        const uint2* vbuf=kbuf+1024;

        float cp0[2][2];
        #pragma unroll
        for (int r=0;r<2;r++){
            const float* yp=ryg+((size_t)bh*NQ+qc[r])*64+2*t;
            cp0[r][0]=yp[0]-shift[r];
            cp0[r][1]=yp[1]-shift[r];
        }
        unsigned mbw[4];
        #pragma unroll
        for (int j=0;j<4;j++) mbw[j]=mbits[b*128+t*4+j];

        if ((mbw[0]|mbw[1]|mbw[2]|mbw[3])==0u){
            #pragma unroll
            for (int ks=0;ks<8;ks++){
                const int yp=ks>>2;
                float sc[2][4];
                #pragma unroll
                for (int j=0;j<2;j++){
                    const int nt=2*ks+j;
                    #pragma unroll
                    for (int i=0;i<4;i++){
                        const int row=i>>1, e=i&1;
                        sc[j][i]=rxv[row][(nt&7)*2+e]+cp0[row][yp];
                    }
                }
                #pragma unroll
                for (int j=0;j<2;j++){
                    uint4 kk=*(const uint4*)(kbuf+(size_t)(2*ks+j)*64+lane*2);
                    mma16816(sc[j], qf[0], make_uint2(kk.x,kk.y));
                    mma16816(sc[j], qf[1], make_uint2(kk.z,kk.w));
                }
                uint32_t pa[4];
                pa[0]=pack_h2(ex2f(sc[0][0]),ex2f(sc[0][1]));
                pa[1]=pack_h2(ex2f(sc[0][2]),ex2f(sc[0][3]));
                pa[2]=pack_h2(ex2f(sc[1][0]),ex2f(sc[1][1]));
                pa[3]=pack_h2(ex2f(sc[1][2]),ex2f(sc[1][3]));
                mma16816(ls, pa, onesb);
                const uint2* vp=vbuf+ks*128+lane*4;
                uint4 va=*(const uint4*)vp, vb2=*(const uint4*)(vp+2);
                mma16816(Oacc[0], pa, make_uint2(va.x,va.y));
                mma16816(Oacc[1], pa, make_uint2(va.z,va.w));
                mma16816(Oacc[2], pa, make_uint2(vb2.x,vb2.y));
                mma16816(Oacc[3], pa, make_uint2(vb2.z,vb2.w));
            }
        } else {
            float cp1[2][2];
            #pragma unroll
            for (int r=0;r<2;r++){
                cp1[r][0]=cp0[r][0]-144.26950408889634f;
                cp1[r][1]=cp0[r][1]-144.26950408889634f;
            }
            #pragma unroll
            for (int ks=0;ks<8;ks++){
                float sc[2][4];
                #pragma unroll
                for (int j=0;j<2;j++)
                    #pragma unroll
                    for (int i=0;i<4;i++) sc[j][i]=0.f;
                #pragma unroll
                for (int j=0;j<2;j++){
                    uint4 kk=*(const uint4*)(kbuf+(size_t)(2*ks+j)*64+lane*2);
                    mma16816(sc[j], qf[0], make_uint2(kk.x,kk.y));
                    mma16816(sc[j], qf[1], make_uint2(kk.z,kk.w));
                }
                float pv[2][4];
                const int yp=ks>>2;
                #pragma unroll
                for (int j=0;j<2;j++){
                    const int nt=2*ks+j;
                    #pragma unroll
                    for (int i=0;i<4;i++){
                        const int row=i>>1, e=i&1;
                        bool mbit=(mbw[nt>>2]>>((nt&3)*8+tg*2+e))&1u;
                        float s=sc[j][i]+rxv[row][(nt&7)*2+e];
                        float cp=mbit?cp1[row][yp]:cp0[row][yp];
                        pv[j][i]=ex2f(s+cp);
                    }
                }
                uint32_t pa[4];
                pa[0]=pack_h2(pv[0][0],pv[0][1]);
                pa[1]=pack_h2(pv[0][2],pv[0][3]);
                pa[2]=pack_h2(pv[1][0],pv[1][1]);
                pa[3]=pack_h2(pv[1][2],pv[1][3]);
                mma16816(ls, pa, onesb);
                const uint2* vp=vbuf+ks*128+lane*4;
                uint4 va=*(const uint4*)vp, vb2=*(const uint4*)(vp+2);
                mma16816(Oacc[0], pa, make_uint2(va.x,va.y));
                mma16816(Oacc[1], pa, make_uint2(va.z,va.w));
                mma16816(Oacc[2], pa, make_uint2(vb2.x,vb2.y));
                mma16816(Oacc[3], pa, make_uint2(vb2.z,vb2.w));
            }
        }
    }

    if (tg==0){
        if (qr[0]<NQ) lp[(size_t)z*BB*HH*NQ + (size_t)bh*NQ + qr[0]] = ls[0];
        if (qr[1]<NQ) lp[(size_t)z*BB*HH*NQ + (size_t)bh*NQ + qr[1]] = ls[2];
    }
    #pragma unroll
    for (int r=0;r<2;r++){
        if (qr[r]<NQ){
            float* dst=aop + (size_t)z*BB*NQ*CC + ((size_t)b*NQ+qr[r])*CC + h*32;
            #pragma unroll
            for (int nv=0;nv<4;nv++){
                float2 o=make_float2(Oacc[nv][2*r], Oacc[nv][2*r+1]);
                *(float2*)&dst[nv*8+tg*2]=o;
            }
        }
    }
}

// =================================================================
// Launch 3: combine ksplit partials + normalize + fp16 hi/lo split
// =================================================================
__global__ __launch_bounds__(256) void pack_ao_kernel(
    const float* __restrict__ aop, const float* __restrict__ lp,
    __half* __restrict__ oh, __half* __restrict__ ol)
{
    int i=blockIdx.x*256+threadIdx.x;
    if (i < BB*NQ*CC){
        int bq=i>>8, q=bq%NQ, b=bq/NQ, h=(i>>5)&7;
        size_t li=(size_t)(b*8+h)*NQ+q;
        float l=0.f, v=0.f;
        #pragma unroll
        for (int zz=0;zz<KSPLIT;zz++){
            l+=lp[(size_t)zz*BB*HH*NQ+li];
            v+=aop[(size_t)zz*BB*NQ*CC+i];
        }
        v/=l;
        __half hh=__float2half_rn(v);
        oh[i]=hh; ol[i]=__float2half_rn(v-__half2float(hh));
    }
}

// =================================================================
// Launch 4: output projection, 3-term hi/lo HMMA. grid (4,57) x128thr
// =================================================================
__global__ __launch_bounds__(128) void gemm_h3_kernel(
    const __half* __restrict__ Ah, const __half* __restrict__ Al,
    const uint2* __restrict__ Wfh, const uint2* __restrict__ Wfl,
    const float* __restrict__ bias, float* __restrict__ out, int M)
{
    const int tid=threadIdx.x, wid=tid>>5, lane=tid&31;
    const int g=lane>>2, tg=lane&3;
    const int wrow=wid>>1, wcol=wid&1;
    const int bm=blockIdx.y*32, bn=blockIdx.x*64;
    const int r0=bm+wrow*16+g, r1=r0+8;
    const int r0c=r0<M?r0:M-1, r1c=r1<M?r1:M-1;
    const int fbase=((bn>>3)+wcol*4)*512+lane;
    float c[4][4]={};
    #pragma unroll
    for (int ks=0;ks<16;ks++){
        const int k0=ks*16+tg*2;
        uint32_t ah[4], al[4];
        ah[0]=*(const uint32_t*)&Ah[r0c*256+k0];
        ah[1]=*(const uint32_t*)&Ah[r1c*256+k0];
        ah[2]=*(const uint32_t*)&Ah[r0c*256+k0+8];
        ah[3]=*(const uint32_t*)&Ah[r1c*256+k0+8];
        al[0]=*(const uint32_t*)&Al[r0c*256+k0];
        al[1]=*(const uint32_t*)&Al[r1c*256+k0];
        al[2]=*(const uint32_t*)&Al[r0c*256+k0+8];
        al[3]=*(const uint32_t*)&Al[r1c*256+k0+8];
        #pragma unroll
        for (int nt=0;nt<4;nt++){
            uint2 bh=Wfh[fbase+nt*512+ks*32];
            uint2 bl=Wfl[fbase+nt*512+ks*32];
            mma16816(c[nt], ah, bh);
            mma16816(c[nt], ah, bl);
            mma16816(c[nt], al, bh);
        }
    }
    const int cn=bn+wcol*32;
    #pragma unroll
    for (int nt=0;nt<4;nt++){
        int col=cn+nt*8+tg*2;
        float b0=bias[col], b1=bias[col+1];
        if (r0<M){ float2 o=make_float2(c[nt][0]+b0,c[nt][1]+b1); *(float2*)&out[r0*256+col]=o; }
        if (r1<M){ float2 o=make_float2(c[nt][2]+b0,c[nt][3]+b1); *(float2*)&out[r1*256+col]=o; }
    }
}

// ---------------- launch ----------------
extern "C" void kernel_launch(void* const* d_in, const int* in_sizes, int n_in,
                              void* d_out, int out_size)
{
    const float* query=(const float*)d_in[1];
    const float* ref  =(const float*)d_in[2];
    const float* kin  =(const float*)d_in[3];
    const float* vin  =(const float*)d_in[4];
    const unsigned char* mask=(const unsigned char*)d_in[6];
    const float* W1x=(const float*)d_in[7];
    const float* b1x=(const float*)d_in[8];
    const float* W2x=(const float*)d_in[9];
    const float* W1y=(const float*)d_in[10];
    const float* b1y=(const float*)d_in[11];
    const float* W2y=(const float*)d_in[12];
    const float* Wq =(const float*)d_in[13];
    const float* bq =(const float*)d_in[14];
    const float* Wk =(const float*)d_in[15];
    const float* bk =(const float*)d_in[16];
    const float* Wv =(const float*)d_in[17];
    const float* bv =(const float*)d_in[18];
    const float* Wp =(const float*)d_in[19];
    const float* bp =(const float*)d_in[20];
    float* out=(float*)d_out;

    void *pq,*pwq,*pwk,*pwv,*pwph,*pwpl,*pw2h,*pw2l;
    void *pkf,*pvf,*pmb,*prx,*pry,*paop,*plp,*paoh,*paol;
    cudaGetSymbolAddress(&pq,  g_q);
    cudaGetSymbolAddress(&pwq, g_wqf);
    cudaGetSymbolAddress(&pwk, g_wkf);
    cudaGetSymbolAddress(&pwv, g_wvf);
    cudaGetSymbolAddress(&pwph,g_wpfh);
    cudaGetSymbolAddress(&pwpl,g_wpfl);
    cudaGetSymbolAddress(&pw2h,g_w2fh);
    cudaGetSymbolAddress(&pw2l,g_w2fl);
    cudaGetSymbolAddress(&pkf, g_kf);
    cudaGetSymbolAddress(&pvf, g_vf);
    cudaGetSymbolAddress(&pmb, g_mb);
    cudaGetSymbolAddress(&prx, g_rx);
    cudaGetSymbolAddress(&pry, g_ry);
    cudaGetSymbolAddress(&paop,g_aop);
    cudaGetSymbolAddress(&plp, g_lp);
    cudaGetSymbolAddress(&paoh,g_aoh);
    cudaGetSymbolAddress(&paol,g_aol);

    const float qscale=(float)(0.17677669529663687 * 1.4426950408889634);
    const int MQ=BB*NQ;

    prep_kernel<<<265,256>>>(Wq,Wk,Wv,Wp,W2x,W2y,mask,
        (uint2*)pwq,(uint2*)pwk,(uint2*)pwv,(uint2*)pwph,(uint2*)pwpl,
        (uint2*)pw2h,(uint2*)pw2l,(unsigned*)pmb);
    mid_kernel<<<3336,256>>>(query,kin,vin,
        (const uint2*)pwq,(const uint2*)pwk,(const uint2*)pwv,bq,bk,bv,
        (float*)pq,(uint2*)pkf,(uint2*)pvf,qscale,
        ref,W1x,b1x,W1y,b1y,
        (const uint2*)pw2h,(const uint2*)pw2l,(float*)prx,(float*)pry);
    attn_hmma_kernel<<<dim3(15,BB*HH,KSPLIT),128>>>(
        (const float*)pq,(const uint2*)pkf,(const uint2*)pvf,
        (const float*)prx,(const float*)pry,(const unsigned*)pmb,(float*)paop,(float*)plp);
    pack_ao_kernel<<<(MQ*CC+255)/256,256>>>((const float*)paop,(const float*)plp,(__half*)paoh,(__half*)paol);
    gemm_h3_kernel<<<dim3(4,(MQ+31)/32),128>>>((const __half*)paoh,(const __half*)paol,
        (const uint2*)pwph,(const uint2*)pwpl,bp,out,MQ);
}

// round 16
// speedup vs baseline: 1.0200x; 1.0197x over previous
#include <cuda_runtime.h>
#include <cuda_fp16.h>
#include <cstdint>

#define BB 2
#define NQ 900
#define CC 256
#define HH 8
#define NN 4096
#define DH 32
#define KSPLIT 2

// -------- scratch --------
__device__ float  g_q  [BB*NQ*CC];          // scaled Q projection (scale*log2e)
__device__ uint2  g_wqf[16384], g_wkf[16384], g_wvf[16384];
__device__ uint2  g_wpfh[16384], g_wpfl[16384];
__device__ uint2  g_w2fh[2048], g_w2fl[2048];
__device__ uint2  g_kf[BB*HH*512*2*32];     // [bh][kt8][ds][lane]
__device__ uint2  g_vf[BB*HH*256*4*32];     // [bh][kt16][nt][lane]
__device__ unsigned g_mb[BB*128];
__device__ float  g_rx[BB*HH*NQ*64];        // scaled by log2e
__device__ float  g_ry[BB*HH*NQ*64];        // scaled by log2e
__device__ float  g_aop[KSPLIT*BB*NQ*CC];   // raw partial O
__device__ float  g_lp [KSPLIT*BB*HH*NQ];   // partial l
__device__ __half g_aoh[BB*NQ*CC];
__device__ __half g_aol[BB*NQ*CC];

__device__ __forceinline__ uint32_t pack_h2(float lo, float hi){
    uint32_t r; asm("cvt.rn.f16x2.f32 %0, %1, %2;" : "=r"(r) : "f"(hi), "f"(lo)); return r;
}
__device__ __forceinline__ float lo_f(uint32_t x){ return __low2float(*(__half2*)&x); }
__device__ __forceinline__ float hi_f(uint32_t x){ return __high2float(*(__half2*)&x); }
__device__ __forceinline__ float ex2f(float x){ float r; asm("ex2.approx.f32 %0, %1;":"=f"(r):"f"(x)); return r; }
__device__ __forceinline__ uint32_t ex2h2(uint32_t x){
    uint32_t r; asm("ex2.approx.f16x2 %0, %1;":"=r"(r):"r"(x)); return r;
}
__device__ __forceinline__ void mma16816(float* c, const uint32_t* a, uint2 b){
    asm volatile("mma.sync.aligned.m16n8k16.row.col.f32.f16.f16.f32 "
      "{%0,%1,%2,%3}, {%4,%5,%6,%7}, {%8,%9}, {%0,%1,%2,%3};"
      : "+f"(c[0]),"+f"(c[1]),"+f"(c[2]),"+f"(c[3])
      : "r"(a[0]),"r"(a[1]),"r"(a[2]),"r"(a[3]),"r"(b.x),"r"(b.y));
}
__device__ __forceinline__ uint32_t smem_u32(const void* p){
    uint32_t a; asm("{ .reg .u64 t; cvta.to.shared.u64 t, %1; cvt.u32.u64 %0, t; }":"=r"(a):"l"(p)); return a;
}
__device__ __forceinline__ void cpa16(uint32_t dst, const void* src){
    asm volatile("cp.async.cg.shared.global [%0], [%1], 16;"::"r"(dst),"l"(src));
}
__device__ __forceinline__ void cpa_commit(){ asm volatile("cp.async.commit_group;":::"memory"); }
template<int N> __device__ __forceinline__ void cpa_wait(){ asm volatile("cp.async.wait_group %0;"::"n"(N):"memory"); }

#define L2E 1.4426950408889634f

// =================================================================
// Launch 0: prep (packW x4 [0,256), packW2 [256,264), mask [264])
// =================================================================
__global__ __launch_bounds__(256) void prep_kernel(
    const float* __restrict__ Wq, const float* __restrict__ Wk, const float* __restrict__ Wv,
    const float* __restrict__ Wp, const float* __restrict__ W2x, const float* __restrict__ W2y,
    const unsigned char* __restrict__ mask,
    uint2* __restrict__ wqf, uint2* __restrict__ wkf, uint2* __restrict__ wvf,
    uint2* __restrict__ wpfh, uint2* __restrict__ wpfl,
    uint2* __restrict__ w2fh, uint2* __restrict__ w2fl, unsigned* __restrict__ mb)
{
    const int blk=blockIdx.x, tid=threadIdx.x;
    if (blk < 256){
        const float* W; uint2 *fh, *fl=nullptr;
        int base;
        if (blk < 64){ W=Wq; fh=wqf; base=0; }
        else if (blk < 128){ W=Wk; fh=wkf; base=64; }
        else if (blk < 192){ W=Wv; fh=wvf; base=128; }
        else { W=Wp; fh=wpfh; fl=wpfl; base=192; }
        int idx=(blk-base)*256+tid;
        int lane=idx&31, ks=(idx>>5)&15, n8=idx>>9;
        int k0=ks*16+(lane&3)*2, n=n8*8+(lane>>2);
        float w00=W[k0*256+n], w01=W[(k0+1)*256+n], w08=W[(k0+8)*256+n], w09=W[(k0+9)*256+n];
        uint2 hi=make_uint2(pack_h2(w00,w01), pack_h2(w08,w09));
        fh[idx]=hi;
        if (fl) fl[idx]=make_uint2(pack_h2(w00-lo_f(hi.x), w01-hi_f(hi.x)),
                                   pack_h2(w08-lo_f(hi.y), w09-hi_f(hi.y)));
        return;
    }
    if (blk < 264){
        int idx=(blk-256)*256+tid;
        int axis=idx>>10, r=idx&1023, lane=r&31, ks=r>>5;
        int j0=ks*16+(lane&3)*2, h=lane>>2;
        const float* W2=axis?W2y:W2x;
        float w00=W2[j0*8+h], w01=W2[(j0+1)*8+h], w08=W2[(j0+8)*8+h], w09=W2[(j0+9)*8+h];
        uint2 hi=make_uint2(pack_h2(w00,w01), pack_h2(w08,w09));
        w2fh[idx]=hi;
        w2fl[idx]=make_uint2(pack_h2(w00-lo_f(hi.x), w01-hi_f(hi.x)),
                             pack_h2(w08-lo_f(hi.y), w09-hi_f(hi.y)));
        return;
    }
    if (tid < BB*128){
        const unsigned char* p=mask+tid*32;
        unsigned v=0;
        #pragma unroll
        for (int i=0;i<32;i++) v |= (p[i]?1u:0u)<<i;
        mb[tid]=v;
    }
}

// =================================================================
// Launch 1: FUSED projections + RPE.  grid 3336.
// =================================================================
__global__ __launch_bounds__(256) void mid_kernel(
    const float* __restrict__ qa, const float* __restrict__ ka, const float* __restrict__ va,
    const uint2* __restrict__ wq, const uint2* __restrict__ wk, const uint2* __restrict__ wv,
    const float* __restrict__ bq, const float* __restrict__ bk, const float* __restrict__ bv,
    float* __restrict__ qout, uint2* __restrict__ Kf, uint2* __restrict__ Vf, float qscale,
    const float* __restrict__ ref,
    const float* __restrict__ W1x, const float* __restrict__ b1x,
    const float* __restrict__ W1y, const float* __restrict__ b1y,
    const uint2* __restrict__ w2fh, const uint2* __restrict__ w2fl,
    float* __restrict__ rx, float* __restrict__ ry)
{
    __shared__ char sraw[9216];
    const int blk=blockIdx.x, tid=threadIdx.x;
    const int wid=tid>>5, lane=tid&31, g=lane>>2, tg=lane&3;

    if (blk < 1536){
        __half (*vs)[72] = (__half(*)[72])sraw;
        const int z=blk>>9, rem=blk&511;
        const int bn=(rem&3)*64, bm=(rem>>2)*64;
        const float* A; const uint2* Wf; const float* bias; int M;
        if (z==0){ A=qa; Wf=wq; bias=bq; M=BB*NQ; }
        else if (z==1){ A=ka; Wf=wk; bias=bk; M=BB*NN; }
        else { A=va; Wf=wv; bias=bv; M=BB*NN; }
        if (bm >= M) return;
        const int wrow=wid>>1, wcol=wid&1;
        const int r0=bm+wrow*16+g, r1=r0+8;
        const int r0c=r0<M?r0:M-1, r1c=r1<M?r1:M-1;
        const uint2* wf=Wf+((bn>>3)+wcol*4)*512+lane;
        float c[4][4]={};
        #pragma unroll
        for (int ks=0;ks<16;ks++){
            const int k0=ks*16+tg*2;
            float2 v0=*(const float2*)&A[r0c*256+k0];
            float2 v1=*(const float2*)&A[r1c*256+k0];
            float2 v2=*(const float2*)&A[r0c*256+k0+8];
            float2 v3=*(const float2*)&A[r1c*256+k0+8];
            uint32_t a[4];
            a[0]=pack_h2(v0.x,v0.y);
            a[1]=pack_h2(v1.x,v1.y);
            a[2]=pack_h2(v2.x,v2.y);
            a[3]=pack_h2(v3.x,v3.y);
            #pragma unroll
            for (int nt=0;nt<4;nt++) mma16816(c[nt], a, wf[nt*512+ks*32]);
        }
        const int cn=bn+wcol*32;
        if (z==0){
            #pragma unroll
            for (int nt=0;nt<4;nt++){
                int col=cn+nt*8+tg*2;
                float b0=bias[col], b1=bias[col+1];
                if (r0<M){ float2 o=make_float2((c[nt][0]+b0)*qscale,(c[nt][1]+b1)*qscale); *(float2*)&qout[r0*256+col]=o; }
                if (r1<M){ float2 o=make_float2((c[nt][2]+b0)*qscale,(c[nt][3]+b1)*qscale); *(float2*)&qout[r1*256+col]=o; }
            }
        } else if (z==1){
            // Kf layout: [bh][kt8][ds][lane]
            const int b=r0>>12;
            const int kt8a=(r0&4095)>>3;
            const int h=(bn>>5)+wcol;
            const size_t base=(size_t)(b*8+h)*32768;
            #pragma unroll
            for (int ds=0;ds<2;ds++){
                const int nlo=2*ds, nhi=2*ds+1;
                int clo=cn+nlo*8+tg*2, chi=cn+nhi*8+tg*2;
                float blo0=bias[clo], blo1=bias[clo+1];
                float bhi0=bias[chi], bhi1=bias[chi+1];
                Kf[base + ((size_t)kt8a*2+ds)*32 + lane] = make_uint2(
                    pack_h2(c[nlo][0]+blo0, c[nlo][1]+blo1),
                    pack_h2(c[nhi][0]+bhi0, c[nhi][1]+bhi1));
                Kf[base + ((size_t)(kt8a+1)*2+ds)*32 + lane] = make_uint2(
                    pack_h2(c[nlo][2]+blo0, c[nlo][3]+blo1),
                    pack_h2(c[nhi][2]+bhi0, c[nhi][3]+bhi1));
            }
        } else {
            // Vf layout: [bh][kt16][nt][lane]
            const int rl0=r0&63, rl1=rl0+8;
            #pragma unroll
            for (int nt=0;nt<4;nt++){
                int col=cn+nt*8+tg*2;
                float b0=bias[col], b1=bias[col+1];
                int cl=col&63;
                *(__half2*)&vs[rl0][cl]=__floats2half2_rn(c[nt][0]+b0,c[nt][1]+b1);
                *(__half2*)&vs[rl1][cl]=__floats2half2_rn(c[nt][2]+b0,c[nt][3]+b1);
            }
            __syncthreads();
            const int b=bm>>12;
            const int hloc=tid>>7;
            const int kt16loc=(tid>>5)&3;
            const int lane2=tid&31;
            const int h=(bn>>5)+hloc;
            const int kt16=((bm&4095)>>4)+kt16loc;
            const int key0=kt16loc*16+(lane2&3)*2;
            const size_t vb=(size_t)(b*8+h)*32768 + (size_t)kt16*128;
            #pragma unroll
            for (int nt=0;nt<4;nt++){
                int d=hloc*32+nt*8+(lane2>>2);
                uint2 o;
                o.x=(uint32_t)__half_as_ushort(vs[key0][d])   | ((uint32_t)__half_as_ushort(vs[key0+1][d])<<16);
                o.y=(uint32_t)__half_as_ushort(vs[key0+8][d]) | ((uint32_t)__half_as_ushort(vs[key0+9][d])<<16);
                Vf[vb + nt*32 + lane2]=o;
            }
        }
        return;
    }

    // ---------------- RPE ----------------
    float2 (*sAB)[512] = (float2(*)[512])sraw;
    const int bq2=blk-1536, b=bq2/NQ, q=bq2-b*NQ;
    float4 box=*(const float4*)&ref[bq2*4];
    float lox=box.x-box.z*0.5f, hix=box.x+box.z*0.5f;
    float loy=box.y-box.w*0.5f, hiy=box.y+box.w*0.5f;
    for (int idx=tid; idx<1024; idx+=256){
        int axis=idx>>9, j=idx&511;
        const float* W1=axis?W1y:W1x;
        float u=W1[j], v=W1[512+j];
        float bb=(axis?b1y:b1x)[j];
        float LO=axis?loy:lox, HI=axis?hiy:hix;
        sAB[axis][j]=make_float2(fmaf(LO,u,fmaf(HI,v,bb)), u+v);
    }
    __syncthreads();
    const int axis=wid>>2, mt=wid&3;
    const float p0=((float)(mt*16+g)+0.5f)*16.f;
    const float p1=p0+128.f;
    const uint2* fh=w2fh+axis*1024+lane;
    const uint2* fl=w2fl+axis*1024+lane;
    const float2* AB=sAB[axis];
    float c[4]={0.f,0.f,0.f,0.f};
    #pragma unroll 4
    for (int ks=0;ks<32;ks++){
        int j0=ks*16+tg*2;
        float2 ab0=AB[j0], ab1=AB[j0+1], ab8=AB[j0+8], ab9=AB[j0+9];
        float h00=fmaxf(fmaf(-p0,ab0.y,ab0.x),0.f);
        float h01=fmaxf(fmaf(-p0,ab1.y,ab1.x),0.f);
        float h10=fmaxf(fmaf(-p1,ab0.y,ab0.x),0.f);
        float h11=fmaxf(fmaf(-p1,ab1.y,ab1.x),0.f);
        float h08=fmaxf(fmaf(-p0,ab8.y,ab8.x),0.f);
        float h09=fmaxf(fmaf(-p0,ab9.y,ab9.x),0.f);
        float h18=fmaxf(fmaf(-p1,ab8.y,ab8.x),0.f);
        float h19=fmaxf(fmaf(-p1,ab9.y,ab9.x),0.f);
        uint32_t ah[4], al[4];
        ah[0]=pack_h2(h00,h01); ah[1]=pack_h2(h10,h11);
        ah[2]=pack_h2(h08,h09); ah[3]=pack_h2(h18,h19);
        al[0]=pack_h2(h00-lo_f(ah[0]), h01-hi_f(ah[0]));
        al[1]=pack_h2(h10-lo_f(ah[1]), h11-hi_f(ah[1]));
        al[2]=pack_h2(h08-lo_f(ah[2]), h09-hi_f(ah[2]));
        al[3]=pack_h2(h18-lo_f(ah[3]), h19-hi_f(ah[3]));
        uint2 bh=fh[ks*32], bl=fl[ks*32];
        mma16816(c, ah, bh);
        mma16816(c, ah, bl);
        mma16816(c, al, bh);
    }
    float* outp=axis?ry:rx;
    const int h2=tg*2, pos0=mt*16+g;
    size_t base0=((size_t)(b*8+h2)*NQ+q)*64;
    size_t base1=((size_t)(b*8+h2+1)*NQ+q)*64;
    outp[base0+pos0]    =c[0]*L2E;
    outp[base1+pos0]    =c[1]*L2E;
    outp[base0+pos0+8]  =c[2]*L2E;
    outp[base1+pos0+8]  =c[3]*L2E;
}

// =================================================================
// Launch 2: HMMA flash attention, f16x2 exp. grid (8,16,2), 256 thr
// =================================================================
__global__ __launch_bounds__(256) void attn_hmma_kernel(
    const float* __restrict__ qp, const uint2* __restrict__ Kf, const uint2* __restrict__ Vf,
    const float* __restrict__ rxg, const float* __restrict__ ryg,
    const unsigned* __restrict__ mbits, float* __restrict__ aop, float* __restrict__ lp)
{
    __shared__ uint2 sbuf[2][2048];
    const int tid=threadIdx.x, wid=tid>>5, lane=tid&31;
    const int g=lane>>2, tg=lane&3;
    const int bh=blockIdx.y, b=bh>>3, h=bh&7;
    const int z=blockIdx.z;
    const int q0=blockIdx.x*128 + wid*16;
    int qr[2]={q0+g, q0+g+8};
    int qc[2]={qr[0]<NQ?qr[0]:NQ-1, qr[1]<NQ?qr[1]:NQ-1};

    const uint2* KfB=Kf+(size_t)bh*32768;
    const uint2* VfB=Vf+(size_t)bh*32768;
    const uint32_t sb0=smem_u32(sbuf);

    {
        const char* ks_=(const char*)(KfB+(size_t)(z*16)*1024);
        const char* vs_=(const char*)(VfB+(size_t)(z*16)*1024);
        uint32_t d=sb0+tid*16;
        cpa16(d,        ks_+tid*16);
        cpa16(d+4096,   ks_+4096+tid*16);
        cpa16(d+8192,   vs_+tid*16);
        cpa16(d+12288,  vs_+4096+tid*16);
        cpa_commit();
    }

    uint32_t qf[2][4];
    #pragma unroll
    for (int ds=0;ds<2;ds++)
        #pragma unroll
        for (int r=0;r<2;r++){
            const float* p=qp+((size_t)b*NQ+qc[r])*CC+h*32+ds*16+tg*2;
            qf[ds][r]  =pack_h2(p[0],p[1]);
            qf[ds][r+2]=pack_h2(p[8],p[9]);
        }

    float rxv[2][16], shift[2];
    #pragma unroll
    for (int r=0;r<2;r++){
        const float* rp=rxg+((size_t)bh*NQ+qc[r])*64;
        float mx=-1e30f;
        #pragma unroll
        for (int j=0;j<8;j++){
            float2 v=*(const float2*)&rp[j*8+tg*2];
            rxv[r][j*2]=v.x; rxv[r][j*2+1]=v.y;
            mx=fmaxf(mx,fmaxf(v.x,v.y));
        }
        mx=fmaxf(mx,__shfl_xor_sync(0xffffffffu,mx,1));
        mx=fmaxf(mx,__shfl_xor_sync(0xffffffffu,mx,2));
        const float* yp=ryg+((size_t)bh*NQ+qc[r])*64;
        float my=-1e30f;
        #pragma unroll
        for (int j=0;j<16;j++) my=fmaxf(my,yp[tg+4*j]);
        my=fmaxf(my,__shfl_xor_sync(0xffffffffu,my,1));
        my=fmaxf(my,__shfl_xor_sync(0xffffffffu,my,2));
        shift[r]=mx+my;
    }

    const uint2 onesb = (lane<4)? make_uint2(0x3C003C00u,0x3C003C00u) : make_uint2(0u,0u);
    float Oacc[4][4];
    #pragma unroll
    for (int i=0;i<4;i++)
        #pragma unroll
        for (int j=0;j<4;j++) Oacc[i][j]=0.f;
    float ls[4]={0.f,0.f,0.f,0.f};

    for (int tt=0; tt<16; tt++){
        const int t=z*16+tt;
        __syncthreads();
        if (tt<15){
            const char* ks_=(const char*)(KfB+(size_t)(t+1)*1024);
            const char* vs_=(const char*)(VfB+(size_t)(t+1)*1024);
            uint32_t d=sb0+((tt+1)&1)*16384+tid*16;
            cpa16(d,        ks_+tid*16);
            cpa16(d+4096,   ks_+4096+tid*16);
            cpa16(d+8192,   vs_+tid*16);
            cpa16(d+12288,  vs_+4096+tid*16);
            cpa_commit();
            cpa_wait<1>();
        } else {
            cpa_wait<0>();
        }
        __syncthreads();

        const uint2* kbuf=sbuf[tt&1];
        const uint2* vbuf=kbuf+1024;

        float cp0[2][2];
        #pragma unroll
        for (int r=0;r<2;r++){
            const float* yp=ryg+((size_t)bh*NQ+qc[r])*64+2*t;
            cp0[r][0]=yp[0]-shift[r];
            cp0[r][1]=yp[1]-shift[r];
        }
        unsigned mbw[4];
        #pragma unroll
        for (int j=0;j<4;j++) mbw[j]=mbits[b*128+t*4+j];

        if ((mbw[0]|mbw[1]|mbw[2]|mbw[3])==0u){
            // -------- fast path: no masked keys --------
            #pragma unroll
            for (int ks=0;ks<8;ks++){
                const int yp=ks>>2;
                float sc[2][4];
                #pragma unroll
                for (int j=0;j<2;j++){
                    const int nt=2*ks+j;
                    #pragma unroll
                    for (int i=0;i<4;i++){
                        const int row=i>>1, e=i&1;
                        sc[j][i]=rxv[row][(nt&7)*2+e]+cp0[row][yp];
                    }
                }
                #pragma unroll
                for (int j=0;j<2;j++){
                    const uint2* kf=kbuf+(2*ks+j)*64+lane;
                    mma16816(sc[j], qf[0], kf[0]);
                    mma16816(sc[j], qf[1], kf[32]);
                }
                uint32_t pa[4];
                pa[0]=ex2h2(pack_h2(sc[0][0],sc[0][1]));
                pa[1]=ex2h2(pack_h2(sc[0][2],sc[0][3]));
                pa[2]=ex2h2(pack_h2(sc[1][0],sc[1][1]));
                pa[3]=ex2h2(pack_h2(sc[1][2],sc[1][3]));
                mma16816(ls, pa, onesb);
                const uint2* vf=vbuf+ks*128+lane;
                #pragma unroll
                for (int nv=0;nv<4;nv++)
                    mma16816(Oacc[nv], pa, vf[nv*32]);
            }
        } else {
            // -------- general path --------
            float cp1[2][2];
            #pragma unroll
            for (int r=0;r<2;r++){
                cp1[r][0]=cp0[r][0]-144.26950408889634f;
                cp1[r][1]=cp0[r][1]-144.26950408889634f;
            }
            #pragma unroll
            for (int ks=0;ks<8;ks++){
                float sc[2][4];
                #pragma unroll
                for (int j=0;j<2;j++)
                    #pragma unroll
                    for (int i=0;i<4;i++) sc[j][i]=0.f;
                #pragma unroll
                for (int j=0;j<2;j++){
                    const uint2* kf=kbuf+(2*ks+j)*64+lane;
                    mma16816(sc[j], qf[0], kf[0]);
                    mma16816(sc[j], qf[1], kf[32]);
                }
                float av[2][4];
                const int yp=ks>>2;
                #pragma unroll
                for (int j=0;j<2;j++){
                    const int nt=2*ks+j;
                    #pragma unroll
                    for (int i=0;i<4;i++){
                        const int row=i>>1, e=i&1;
                        bool mbit=(mbw[nt>>2]>>((nt&3)*8+tg*2+e))&1u;
                        float s=sc[j][i]+rxv[row][(nt&7)*2+e];
                        float cp=mbit?cp1[row][yp]:cp0[row][yp];
                        av[j][i]=s+cp;
                    }
                }
                uint32_t pa[4];
                pa[0]=ex2h2(pack_h2(av[0][0],av[0][1]));
                pa[1]=ex2h2(pack_h2(av[0][2],av[0][3]));
                pa[2]=ex2h2(pack_h2(av[1][0],av[1][1]));
                pa[3]=ex2h2(pack_h2(av[1][2],av[1][3]));
                mma16816(ls, pa, onesb);
                const uint2* vf=vbuf+ks*128+lane;
                #pragma unroll
                for (int nv=0;nv<4;nv++)
                    mma16816(Oacc[nv], pa, vf[nv*32]);
            }
        }
    }

    if (tg==0){
        if (qr[0]<NQ) lp[(size_t)z*BB*HH*NQ + (size_t)bh*NQ + qr[0]] = ls[0];
        if (qr[1]<NQ) lp[(size_t)z*BB*HH*NQ + (size_t)bh*NQ + qr[1]] = ls[2];
    }
    #pragma unroll
    for (int r=0;r<2;r++){
        if (qr[r]<NQ){
            float* dst=aop + (size_t)z*BB*NQ*CC + ((size_t)b*NQ+qr[r])*CC + h*32;
            #pragma unroll
            for (int nv=0;nv<4;nv++){
                float2 o=make_float2(Oacc[nv][2*r], Oacc[nv][2*r+1]);
                *(float2*)&dst[nv*8+tg*2]=o;
            }
        }
    }
}

// =================================================================
// Launch 3: combine ksplit partials + normalize + fp16 hi/lo split
// =================================================================
__global__ __launch_bounds__(256) void pack_ao_kernel(
    const float* __restrict__ aop, const float* __restrict__ lp,
    __half* __restrict__ oh, __half* __restrict__ ol)
{
    int i=blockIdx.x*256+threadIdx.x;
    if (i < BB*NQ*CC){
        int bq=i>>8, q=bq%NQ, b=bq/NQ, h=(i>>5)&7;
        size_t li=(size_t)(b*8+h)*NQ+q;
        float l=0.f, v=0.f;
        #pragma unroll
        for (int zz=0;zz<KSPLIT;zz++){
            l+=lp[(size_t)zz*BB*HH*NQ+li];
            v+=aop[(size_t)zz*BB*NQ*CC+i];
        }
        v/=l;
        __half hh=__float2half_rn(v);
        oh[i]=hh; ol[i]=__float2half_rn(v-__half2float(hh));
    }
}

// =================================================================
// Launch 4: output projection, 3-term hi/lo HMMA. grid (4,57) x128thr
// =================================================================
__global__ __launch_bounds__(128) void gemm_h3_kernel(
    const __half* __restrict__ Ah, const __half* __restrict__ Al,
    const uint2* __restrict__ Wfh, const uint2* __restrict__ Wfl,
    const float* __restrict__ bias, float* __restrict__ out, int M)
{
    const int tid=threadIdx.x, wid=tid>>5, lane=tid&31;
    const int g=lane>>2, tg=lane&3;
    const int wrow=wid>>1, wcol=wid&1;
    const int bm=blockIdx.y*32, bn=blockIdx.x*64;
    const int r0=bm+wrow*16+g, r1=r0+8;
    const int r0c=r0<M?r0:M-1, r1c=r1<M?r1:M-1;
    const int fbase=((bn>>3)+wcol*4)*512+lane;
    float c[4][4]={};
    #pragma unroll
    for (int ks=0;ks<16;ks++){
        const int k0=ks*16+tg*2;
        uint32_t ah[4], al[4];
        ah[0]=*(const uint32_t*)&Ah[r0c*256+k0];
        ah[1]=*(const uint32_t*)&Ah[r1c*256+k0];
        ah[2]=*(const uint32_t*)&Ah[r0c*256+k0+8];
        ah[3]=*(const uint32_t*)&Ah[r1c*256+k0+8];
        al[0]=*(const uint32_t*)&Al[r0c*256+k0];
        al[1]=*(const uint32_t*)&Al[r1c*256+k0];
        al[2]=*(const uint32_t*)&Al[r0c*256+k0+8];
        al[3]=*(const uint32_t*)&Al[r1c*256+k0+8];
        #pragma unroll
        for (int nt=0;nt<4;nt++){
            uint2 bh=Wfh[fbase+nt*512+ks*32];
            uint2 bl=Wfl[fbase+nt*512+ks*32];
            mma16816(c[nt], ah, bh);
            mma16816(c[nt], ah, bl);
            mma16816(c[nt], al, bh);
        }
    }
    const int cn=bn+wcol*32;
    #pragma unroll
    for (int nt=0;nt<4;nt++){
        int col=cn+nt*8+tg*2;
        float b0=bias[col], b1=bias[col+1];
        if (r0<M){ float2 o=make_float2(c[nt][0]+b0,c[nt][1]+b1); *(float2*)&out[r0*256+col]=o; }
        if (r1<M){ float2 o=make_float2(c[nt][2]+b0,c[nt][3]+b1); *(float2*)&out[r1*256+col]=o; }
    }
}

// ---------------- launch ----------------
extern "C" void kernel_launch(void* const* d_in, const int* in_sizes, int n_in,
                              void* d_out, int out_size)
{
    const float* query=(const float*)d_in[1];
    const float* ref  =(const float*)d_in[2];
    const float* kin  =(const float*)d_in[3];
    const float* vin  =(const float*)d_in[4];
    const unsigned char* mask=(const unsigned char*)d_in[6];
    const float* W1x=(const float*)d_in[7];
    const float* b1x=(const float*)d_in[8];
    const float* W2x=(const float*)d_in[9];
    const float* W1y=(const float*)d_in[10];
    const float* b1y=(const float*)d_in[11];
    const float* W2y=(const float*)d_in[12];
    const float* Wq =(const float*)d_in[13];
    const float* bq =(const float*)d_in[14];
    const float* Wk =(const float*)d_in[15];
    const float* bk =(const float*)d_in[16];
    const float* Wv =(const float*)d_in[17];
    const float* bv =(const float*)d_in[18];
    const float* Wp =(const float*)d_in[19];
    const float* bp =(const float*)d_in[20];
    float* out=(float*)d_out;

    void *pq,*pwq,*pwk,*pwv,*pwph,*pwpl,*pw2h,*pw2l;
    void *pkf,*pvf,*pmb,*prx,*pry,*paop,*plp,*paoh,*paol;
    cudaGetSymbolAddress(&pq,  g_q);
    cudaGetSymbolAddress(&pwq, g_wqf);
    cudaGetSymbolAddress(&pwk, g_wkf);
    cudaGetSymbolAddress(&pwv, g_wvf);
    cudaGetSymbolAddress(&pwph,g_wpfh);
    cudaGetSymbolAddress(&pwpl,g_wpfl);
    cudaGetSymbolAddress(&pw2h,g_w2fh);
    cudaGetSymbolAddress(&pw2l,g_w2fl);
    cudaGetSymbolAddress(&pkf, g_kf);
    cudaGetSymbolAddress(&pvf, g_vf);
    cudaGetSymbolAddress(&pmb, g_mb);
    cudaGetSymbolAddress(&prx, g_rx);
    cudaGetSymbolAddress(&pry, g_ry);
    cudaGetSymbolAddress(&paop,g_aop);
    cudaGetSymbolAddress(&plp, g_lp);
    cudaGetSymbolAddress(&paoh,g_aoh);
    cudaGetSymbolAddress(&paol,g_aol);

    const float qscale=(float)(0.17677669529663687 * 1.4426950408889634);
    const int MQ=BB*NQ;

    prep_kernel<<<265,256>>>(Wq,Wk,Wv,Wp,W2x,W2y,mask,
        (uint2*)pwq,(uint2*)pwk,(uint2*)pwv,(uint2*)pwph,(uint2*)pwpl,
        (uint2*)pw2h,(uint2*)pw2l,(unsigned*)pmb);
    mid_kernel<<<3336,256>>>(query,kin,vin,
        (const uint2*)pwq,(const uint2*)pwk,(const uint2*)pwv,bq,bk,bv,
        (float*)pq,(uint2*)pkf,(uint2*)pvf,qscale,
        ref,W1x,b1x,W1y,b1y,
        (const uint2*)pw2h,(const uint2*)pw2l,(float*)prx,(float*)pry);
    attn_hmma_kernel<<<dim3(8,BB*HH,KSPLIT),256>>>(
        (const float*)pq,(const uint2*)pkf,(const uint2*)pvf,
        (const float*)prx,(const float*)pry,(const unsigned*)pmb,(float*)paop,(float*)plp);
    pack_ao_kernel<<<(MQ*CC+255)/256,256>>>((const float*)paop,(const float*)plp,(__half*)paoh,(__half*)paol);
    gemm_h3_kernel<<<dim3(4,(MQ+31)/32),128>>>((const __half*)paoh,(const __half*)paol,
        (const uint2*)pwph,(const uint2*)pwpl,bp,out,MQ);
}